// round 9
// baseline (speedup 1.0000x reference)
#include <cuda_runtime.h>
#include <cstdint>

#define Nn 2048
#define Dd 64
#define Vv 2048
#define TB 128                      // pair tile dim
#define NT (Nn / TB)                // 16
#define NTILES (NT * (NT + 1) / 2)  // 136 triangle tiles
#define PADK 33                     // float2 row stride (pad) -> conflict-free
#define NTHR 512
#define MAXBLK 1024                 // k_pre max-reduction blocks

// Scratch (no allocations -> __device__ globals). All overwritten per call.
__device__ float g_part[MAXBLK];            // per-block maxes of map
__device__ float g_rowsum[Nn];              // S[i] = sum_d emb[i][d]
__device__ float g_psum[NTILES], g_pcnt[NTILES];
__device__ unsigned g_ctr;                  // zero-init; last block resets to 0

// ---------------------------------------------------------------------------
__device__ __forceinline__ void cpa4(uint32_t dst, const float* src) {
    asm volatile("cp.async.ca.shared.global [%0], [%1], 4;" :: "r"(dst), "l"(src));
}

// ---------------------------------------------------------------------------
// blocks 0..1023: map max (256 thr x 4 float4 = 16KB/block, MLP 4)
// blocks 1024..1031: row sums of emb (one row per thread)
__global__ __launch_bounds__(256) void k_pre(const float4* __restrict__ mapd,
                                             const float4* __restrict__ emb) {
    int bid = blockIdx.x, tid = threadIdx.x;
    if (bid < MAXBLK) {
        const float4* p = mapd + (size_t)bid * 1024;
        float4 x0 = p[tid];
        float4 x1 = p[tid + 256];
        float4 x2 = p[tid + 512];
        float4 x3 = p[tid + 768];
        float v = fmaxf(fmaxf(fmaxf(x0.x, x0.y), fmaxf(x0.z, x0.w)),
                        fmaxf(fmaxf(x1.x, x1.y), fmaxf(x1.z, x1.w)));
        v = fmaxf(v, fmaxf(fmaxf(fmaxf(x2.x, x2.y), fmaxf(x2.z, x2.w)),
                           fmaxf(fmaxf(x3.x, x3.y), fmaxf(x3.z, x3.w))));
#pragma unroll
        for (int o = 16; o; o >>= 1) v = fmaxf(v, __shfl_xor_sync(0xffffffffu, v, o));
        __shared__ float sred[8];
        int lane = tid & 31, w = tid >> 5;
        if (lane == 0) sred[w] = v;
        __syncthreads();
        if (tid == 0) {
            float m = sred[0];
#pragma unroll
            for (int i = 1; i < 8; i++) m = fmaxf(m, sred[i]);
            g_part[bid] = m;
        }
    } else {
        int row = (bid - MAXBLK) * 256 + tid;   // 2048 rows
        const float4* e = emb + row * (Dd / 4);
        float s = 0.0f;
#pragma unroll
        for (int k = 0; k < Dd / 4; k++) {
            float4 x = e[k];
            s += (x.x + x.y) + (x.z + x.w);
        }
        g_rowsum[row] = s;
    }
}

// ---------------------------------------------------------------------------
extern __shared__ unsigned long long smem_raw[];

// 512 threads (R2's proven shape): thread (tx=tid&15, ty=tid>>4) owns rows
// ty + 32r (r<4), cols tx + 16c (c<8). Inner op per element: FMNMX (alu) +
// FADD (fma) -- balanced dual-pipe; Sum|a-b| = 2*Sum max - S_i - S_j.
// tree/map gathers issued via cp.async before the mainloop (latency hidden).
// Last finishing block folds the global reduction.
__global__ __launch_bounds__(NTHR, 1) void k_main(const int* __restrict__ ids,
                                                  const float2* __restrict__ emb,
                                                  const float* __restrict__ tree,
                                                  const float* __restrict__ mapd,
                                                  float* __restrict__ out) {
    int tid = threadIdx.x;
    int t = blockIdx.x, bi = 0;
    while (t >= NT - bi) { t -= NT - bi; bi++; }
    int bj = bi + t;
    int ibase = bi * TB, jbase = bj * TB;
    bool offdiag = (bi != bj);

    float2* sA = (float2*)smem_raw;                 // [128][PADK]
    float2* sB = sA + TB * PADK;
    int*   sIdI = (int*)(sB + TB * PADK);
    int*   sIdJ = sIdI + TB;
    float* sSA  = (float*)(sIdJ + TB);              // row sums i-tile
    float* sSB  = sSA + TB;                         // row sums j-tile
    float* sSc  = sSB + TB;                         // [0] = 0.5/max
    float* sMT  = sSc + 4;                          // [32][512] tree gathers
    float* sMM  = sMT + 32 * NTHR;                  // [32][512] map gathers
    __shared__ float sred[32];

    int tx = tid & 15, ty = tid >> 4;

    // role-split preload (ids needed before gathers can be issued)
    if (tid < TB)            sIdI[tid] = ids[ibase + tid];
    else if (tid < 2 * TB)   sIdJ[tid - TB] = ids[jbase + tid - TB];
    else if (tid < 3 * TB)   sSA[tid - 2 * TB] = g_rowsum[ibase + tid - 2 * TB];
    else if (tid < 4 * TB)   sSB[tid - 3 * TB] = g_rowsum[jbase + tid - 3 * TB];
    if (tid < 32) {          // warp 0 (after its id loads): 1024 maxes -> sc
        float v = 0.0f;
        for (int k = tid; k < MAXBLK; k += 32) v = fmaxf(v, g_part[k]);
#pragma unroll
        for (int o = 16; o; o >>= 1) v = fmaxf(v, __shfl_xor_sync(0xffffffffu, v, o));
        if (tid == 0) sSc[0] = 0.5f / v;
    }
    __syncthreads();

    // issue all metric gathers now; they complete under the mainloop
    {
        uint32_t dT = (uint32_t)__cvta_generic_to_shared(sMT) + tid * 4u;
        uint32_t dM = (uint32_t)__cvta_generic_to_shared(sMM) + tid * 4u;
#pragma unroll
        for (int r = 0; r < 4; r++) {
            int off0 = sIdI[ty + 32 * r] * Vv;
#pragma unroll
            for (int c = 0; c < 8; c++) {
                int idx = off0 + sIdJ[tx + 16 * c];
                uint32_t po = (uint32_t)(r * 8 + c) * (NTHR * 4u);
                cpa4(dT + po, tree + idx);
                cpa4(dM + po, mapd + idx);
            }
        }
        asm volatile("cp.async.commit_group;");
    }

    // embedding tiles (coalesced)
    for (int x = tid; x < TB * 32; x += NTHR) {
        int row = x >> 5, k2 = x & 31;
        sA[row * PADK + k2] = emb[(ibase + row) * 32 + k2];
        sB[row * PADK + k2] = emb[(jbase + row) * 32 + k2];
    }
    __syncthreads();

    float acc[4][8];
#pragma unroll
    for (int r = 0; r < 4; r++)
#pragma unroll
        for (int c = 0; c < 8; c++) acc[r][c] = 0.0f;

    const float2* sArow = sA + ty * PADK;
    const float2* sBrow = sB + tx * PADK;

#pragma unroll 4
    for (int k2 = 0; k2 < 32; k2++) {
        float2 b2[8];
#pragma unroll
        for (int c = 0; c < 8; c++) b2[c] = sBrow[(16 * c) * PADK + k2];
#pragma unroll
        for (int r = 0; r < 4; r++) {
            float2 a = sArow[(32 * r) * PADK + k2];
#pragma unroll
            for (int c = 0; c < 8; c++) {
                acc[r][c] += fmaxf(a.x, b2[c].x);   // FMNMX (alu) + FADD (fma)
                acc[r][c] += fmaxf(a.y, b2[c].y);
            }
        }
    }

    asm volatile("cp.async.wait_group 0;" ::: "memory");

    // epilogue: ed = (2*sum(max) - S_i - S_j)/64 ; metric = 0.5*t + sc*m
    float sc = sSc[0];
    float loss = 0.0f, cnt = 0.0f;
    const float inv64 = 1.0f / 64.0f;
#pragma unroll
    for (int r = 0; r < 4; r++) {
        int ir = ty + 32 * r;
        int idi = sIdI[ir];
        int gi  = ibase + ir;
        float Si = sSA[ir];
#pragma unroll
        for (int c = 0; c < 8; c++) {
            int jc = tx + 16 * c;
            int idj = sIdJ[jc];
            int gj  = jbase + jc;
            if ((offdiag || gi < gj) && idi != idj) {
                float ed = (2.0f * acc[r][c] - Si - sSB[jc]) * inv64;
                int p = (r * 8 + c) * NTHR + tid;
                float metric = fmaf(sc, sMM[p], 0.5f * sMT[p]);
                loss += fabsf(ed - metric);
                cnt += 1.0f;
            }
        }
    }

#pragma unroll
    for (int o = 16; o; o >>= 1) {
        loss += __shfl_xor_sync(0xffffffffu, loss, o);
        cnt  += __shfl_xor_sync(0xffffffffu, cnt, o);
    }
    int lane = tid & 31, w = tid >> 5;
    if (lane == 0) { sred[w] = loss; sred[16 + w] = cnt; }
    __syncthreads();
    if (tid == 0) {
        float L = 0.0f, C = 0.0f;
#pragma unroll
        for (int i = 0; i < 16; i++) { L += sred[i]; C += sred[16 + i]; }
        g_psum[blockIdx.x] = L;
        g_pcnt[blockIdx.x] = C;
        __threadfence();
        unsigned done = atomicAdd(&g_ctr, 1u);
        sred[0] = (done == NTILES - 1) ? 1.0f : 0.0f;
    }
    __syncthreads();
    if (sred[0] != 0.0f) {            // last block folds the final reduction
        __threadfence();
        float L = 0.0f, C = 0.0f;
        if (tid < NTILES) {
            L = *((volatile float*)g_psum + tid);
            C = *((volatile float*)g_pcnt + tid);
        }
#pragma unroll
        for (int o = 16; o; o >>= 1) {
            L += __shfl_xor_sync(0xffffffffu, L, o);
            C += __shfl_xor_sync(0xffffffffu, C, o);
        }
        if (lane == 0) { sred[w] = L; sred[16 + w] = C; }
        __syncthreads();
        if (tid == 0) {
            float LL = 0.0f, CC = 0.0f;
#pragma unroll
            for (int i = 0; i < 5; i++) { LL += sred[i]; CC += sred[16 + i]; }
            out[0] = LL / CC;
            g_ctr = 0u;               // self-reset for next graph replay
        }
    }
}

// ---------------------------------------------------------------------------
extern "C" void kernel_launch(void* const* d_in, const int* in_sizes, int n_in,
                              void* d_out, int out_size) {
    const int*   ids  = (const int*)d_in[0];
    const float* emb  = (const float*)d_in[1];
    const float* tree = (const float*)d_in[2];
    const float* mapd = (const float*)d_in[3];
    float* out = (float*)d_out;

    // smem: tiles 67584 + ids/rowsums 2048 + sc 16 + gather 2*32*512*4=131072
    const int SMEM_BYTES = 2 * TB * PADK * 8 + 4 * TB * 4 + 16 + 64 * NTHR * 4;
    cudaFuncSetAttribute(k_main, cudaFuncAttributeMaxDynamicSharedMemorySize,
                         SMEM_BYTES);

    k_pre<<<MAXBLK + Nn / 256, 256>>>((const float4*)mapd, (const float4*)emb);
    k_main<<<NTILES, NTHR, SMEM_BYTES>>>(ids, (const float2*)emb, tree, mapd, out);
}

// round 10
// speedup vs baseline: 1.6178x; 1.6178x over previous
#include <cuda_runtime.h>
#include <cstdint>

#define Nn 2048
#define Dd 64
#define Vv 2048
#define TB 128                      // pair tile dim
#define NT (Nn / TB)                // 16
#define NTILES (NT * (NT + 1) / 2)  // 136 triangle tiles
#define PADK 33                     // float2 row stride (pad) -> conflict-free
#define NTHR 512
#define MAXBLK 1024                 // k_pre max-reduction blocks

// Scratch (no allocations -> __device__ globals). All overwritten per call.
__device__ float g_table[(size_t)Vv * Vv];  // fused metric table, 16MB
__device__ float g_part[MAXBLK];            // per-block maxes of map
__device__ float g_rowsum[Nn];              // S[i] = sum_d emb[i][d]
__device__ float g_psum[NTILES], g_pcnt[NTILES];
__device__ unsigned g_ctr;                  // zero-init; last block resets to 0

// ---------------------------------------------------------------------------
// blocks 0..1023: map max (256 thr x 4 float4 = 16KB/block, MLP 4)
// blocks 1024..1031: row sums of emb (one row per thread)
__global__ __launch_bounds__(256) void k_pre(const float4* __restrict__ mapd,
                                             const float4* __restrict__ emb) {
    int bid = blockIdx.x, tid = threadIdx.x;
    if (bid < MAXBLK) {
        const float4* p = mapd + (size_t)bid * 1024;
        float4 x0 = p[tid];
        float4 x1 = p[tid + 256];
        float4 x2 = p[tid + 512];
        float4 x3 = p[tid + 768];
        float v = fmaxf(fmaxf(fmaxf(x0.x, x0.y), fmaxf(x0.z, x0.w)),
                        fmaxf(fmaxf(x1.x, x1.y), fmaxf(x1.z, x1.w)));
        v = fmaxf(v, fmaxf(fmaxf(fmaxf(x2.x, x2.y), fmaxf(x2.z, x2.w)),
                           fmaxf(fmaxf(x3.x, x3.y), fmaxf(x3.z, x3.w))));
#pragma unroll
        for (int o = 16; o; o >>= 1) v = fmaxf(v, __shfl_xor_sync(0xffffffffu, v, o));
        __shared__ float sred[8];
        int lane = tid & 31, w = tid >> 5;
        if (lane == 0) sred[w] = v;
        __syncthreads();
        if (tid == 0) {
            float m = sred[0];
#pragma unroll
            for (int i = 1; i < 8; i++) m = fmaxf(m, sred[i]);
            g_part[bid] = m;
        }
    } else {
        int row = (bid - MAXBLK) * 256 + tid;   // 2048 rows
        const float4* e = emb + row * (Dd / 4);
        float s = 0.0f;
#pragma unroll
        for (int k = 0; k < Dd / 4; k++) {
            float4 x = e[k];
            s += (x.x + x.y) + (x.z + x.w);
        }
        g_rowsum[row] = s;
    }
}

// ---------------------------------------------------------------------------
// fused metric table: table = 0.5*tree + (0.5/largest)*map
// grid = 1024 blocks x 1024 threads, one float4 per thread (streaming).
__global__ __launch_bounds__(1024) void k_table(const float4* __restrict__ tree,
                                                const float4* __restrict__ mapd) {
    __shared__ float ssc;
    if (threadIdx.x < 32) {
        float v = 0.0f;
        for (int k = threadIdx.x; k < MAXBLK; k += 32) v = fmaxf(v, g_part[k]);
#pragma unroll
        for (int o = 16; o; o >>= 1) v = fmaxf(v, __shfl_xor_sync(0xffffffffu, v, o));
        if (threadIdx.x == 0) ssc = 0.5f / v;
    }
    __syncthreads();
    float sc = ssc;
    int i = blockIdx.x * 1024 + threadIdx.x;   // covers V*V/4
    float4 t = tree[i], m = mapd[i];
    float4 o;
    o.x = 0.5f * t.x + sc * m.x;
    o.y = 0.5f * t.y + sc * m.y;
    o.z = 0.5f * t.z + sc * m.z;
    o.w = 0.5f * t.w + sc * m.w;
    ((float4*)g_table)[i] = o;
}

// ---------------------------------------------------------------------------
extern __shared__ unsigned long long smem_raw[];

// 512 threads (R2's proven shape): thread (tx=tid&15, ty=tid>>4) owns rows
// ty + 32r (r<4), cols tx + 16c (c<8). Inner op: FMNMX (alu) + FADD (fma);
// Sum|a-b| = 2*Sum max - S_i - S_j. Table gathers are issued into REGISTERS
// mid-mainloop (ld.global.nc, asm-pinned) so their L1tex wavefront work
// overlaps the second half of the math. Last block folds the reduction.
__global__ __launch_bounds__(NTHR, 1) void k_main(const int* __restrict__ ids,
                                                  const float2* __restrict__ emb,
                                                  float* __restrict__ out) {
    int tid = threadIdx.x;
    int t = blockIdx.x, bi = 0;
    while (t >= NT - bi) { t -= NT - bi; bi++; }
    int bj = bi + t;
    int ibase = bi * TB, jbase = bj * TB;
    bool offdiag = (bi != bj);

    float2* sA = (float2*)smem_raw;                 // [128][PADK]
    float2* sB = sA + TB * PADK;
    int*   sIdI = (int*)(sB + TB * PADK);
    int*   sIdJ = sIdI + TB;
    float* sSA  = (float*)(sIdJ + TB);              // row sums i-tile
    float* sSB  = sSA + TB;                         // row sums j-tile
    __shared__ float sred[32];

    int tx = tid & 15, ty = tid >> 4;

    // role-split preload
    if (tid < TB)            sIdI[tid] = ids[ibase + tid];
    else if (tid < 2 * TB)   sIdJ[tid - TB] = ids[jbase + tid - TB];
    else if (tid < 3 * TB)   sSA[tid - 2 * TB] = g_rowsum[ibase + tid - 2 * TB];
    else                     sSB[tid - 3 * TB] = g_rowsum[jbase + tid - 3 * TB];

    // embedding tiles (coalesced)
    for (int x = tid; x < TB * 32; x += NTHR) {
        int row = x >> 5, k2 = x & 31;
        sA[row * PADK + k2] = emb[(ibase + row) * 32 + k2];
        sB[row * PADK + k2] = emb[(jbase + row) * 32 + k2];
    }
    __syncthreads();

    float acc[4][8];
#pragma unroll
    for (int r = 0; r < 4; r++)
#pragma unroll
        for (int c = 0; c < 8; c++) acc[r][c] = 0.0f;

    const float2* sArow = sA + ty * PADK;
    const float2* sBrow = sB + tx * PADK;

    // ---- mainloop first half: k2 = 0..15 ----
#pragma unroll 4
    for (int k2 = 0; k2 < 16; k2++) {
        float2 b2[8];
#pragma unroll
        for (int c = 0; c < 8; c++) b2[c] = sBrow[(16 * c) * PADK + k2];
#pragma unroll
        for (int r = 0; r < 4; r++) {
            float2 a = sArow[(32 * r) * PADK + k2];
#pragma unroll
            for (int c = 0; c < 8; c++) {
                acc[r][c] += fmaxf(a.x, b2[c].x);
                acc[r][c] += fmaxf(a.y, b2[c].y);
            }
        }
    }

    // ---- mid-loop: issue all 32 table gathers into registers ----
    float gmet[32];
    {
#pragma unroll
        for (int r = 0; r < 4; r++) {
            const float* rowp = g_table + (size_t)sIdI[ty + 32 * r] * Vv;
#pragma unroll
            for (int c = 0; c < 8; c++) {
                asm volatile("ld.global.nc.f32 %0, [%1];"
                             : "=f"(gmet[r * 8 + c])
                             : "l"(rowp + sIdJ[tx + 16 * c]));
            }
        }
    }

    // ---- mainloop second half: k2 = 16..31 (overlaps gather latency) ----
#pragma unroll 4
    for (int k2 = 16; k2 < 32; k2++) {
        float2 b2[8];
#pragma unroll
        for (int c = 0; c < 8; c++) b2[c] = sBrow[(16 * c) * PADK + k2];
#pragma unroll
        for (int r = 0; r < 4; r++) {
            float2 a = sArow[(32 * r) * PADK + k2];
#pragma unroll
            for (int c = 0; c < 8; c++) {
                acc[r][c] += fmaxf(a.x, b2[c].x);
                acc[r][c] += fmaxf(a.y, b2[c].y);
            }
        }
    }

    // epilogue: ed = (2*sum(max) - S_i - S_j)/64 ; metric = gmet
    float loss = 0.0f, cnt = 0.0f;
    const float inv64 = 1.0f / 64.0f;
#pragma unroll
    for (int r = 0; r < 4; r++) {
        int ir = ty + 32 * r;
        int idi = sIdI[ir];
        int gi  = ibase + ir;
        float Si = sSA[ir];
#pragma unroll
        for (int c = 0; c < 8; c++) {
            int jc = tx + 16 * c;
            int idj = sIdJ[jc];
            int gj  = jbase + jc;
            if ((offdiag || gi < gj) && idi != idj) {
                float ed = (2.0f * acc[r][c] - Si - sSB[jc]) * inv64;
                loss += fabsf(ed - gmet[r * 8 + c]);
                cnt += 1.0f;
            }
        }
    }

#pragma unroll
    for (int o = 16; o; o >>= 1) {
        loss += __shfl_xor_sync(0xffffffffu, loss, o);
        cnt  += __shfl_xor_sync(0xffffffffu, cnt, o);
    }
    int lane = tid & 31, w = tid >> 5;
    if (lane == 0) { sred[w] = loss; sred[16 + w] = cnt; }
    __syncthreads();
    if (tid == 0) {
        float L = 0.0f, C = 0.0f;
#pragma unroll
        for (int i = 0; i < 16; i++) { L += sred[i]; C += sred[16 + i]; }
        g_psum[blockIdx.x] = L;
        g_pcnt[blockIdx.x] = C;
        __threadfence();
        unsigned done = atomicAdd(&g_ctr, 1u);
        sred[0] = (done == NTILES - 1) ? 1.0f : 0.0f;
    }
    __syncthreads();
    if (sred[0] != 0.0f) {            // last block folds the final reduction
        __threadfence();
        float L = 0.0f, C = 0.0f;
        if (tid < NTILES) {
            L = *((volatile float*)g_psum + tid);
            C = *((volatile float*)g_pcnt + tid);
        }
#pragma unroll
        for (int o = 16; o; o >>= 1) {
            L += __shfl_xor_sync(0xffffffffu, L, o);
            C += __shfl_xor_sync(0xffffffffu, C, o);
        }
        if (lane == 0) { sred[w] = L; sred[16 + w] = C; }
        __syncthreads();
        if (tid == 0) {
            float LL = 0.0f, CC = 0.0f;
#pragma unroll
            for (int i = 0; i < 5; i++) { LL += sred[i]; CC += sred[16 + i]; }
            out[0] = LL / CC;
            g_ctr = 0u;               // self-reset for next graph replay
        }
    }
}

// ---------------------------------------------------------------------------
extern "C" void kernel_launch(void* const* d_in, const int* in_sizes, int n_in,
                              void* d_out, int out_size) {
    const int*   ids  = (const int*)d_in[0];
    const float* emb  = (const float*)d_in[1];
    const float* tree = (const float*)d_in[2];
    const float* mapd = (const float*)d_in[3];
    float* out = (float*)d_out;

    // smem: tiles 67584 + ids 1024 + rowsums 1024 = 69632 B
    const int SMEM_BYTES = 2 * TB * PADK * 8 + 2 * TB * 4 + 2 * TB * 4;
    cudaFuncSetAttribute(k_main, cudaFuncAttributeMaxDynamicSharedMemorySize,
                         SMEM_BYTES);

    k_pre<<<MAXBLK + Nn / 256, 256>>>((const float4*)mapd, (const float4*)emb);
    k_table<<<(Vv * Vv / 4) / 1024, 1024>>>((const float4*)tree,
                                            (const float4*)mapd);
    k_main<<<NTILES, NTHR, SMEM_BYTES>>>(ids, (const float2*)emb, out);
}